// round 3
// baseline (speedup 1.0000x reference)
#include <cuda_runtime.h>
#include <cstdint>
#include <math.h>

// MultiVectorQuantizer: 4 groups, K=512 codes, D=128. Bit-replicates the
// reference's fp32 dist = (x_sq + w_sq) - 2*cross rounding via integer scores
// on the ulp(x_sq) grid:  score_k = rhe(w_sq_k/u) - rhe(2*cross_k/u),
// which is independent of x_sq's exact value given its binade.

#define TM 128
#define NC 64
#define KD 128
#define KCODES 512
#define NTHREADS 256

__device__ double g_loss[4];
__device__ float  g_wsq[4 * KCODES];

struct SMem {
    double lred[8];
    float  X[KD][TM + 4];     // [d][token]
    float  W[KD][NC + 4];     // [d][code]
    float  wsq[NC];
    float  invU[TM];          // 2^(23-E) where E = exponent(x_sq)
    float  sc2[TM];           // 2*invU
    float  t0[TM];            // (2^E - x_sq)*invU  (<= 0, on-grid integer)
    int    idx[TM];
};

__global__ void prep_kernel(const float* __restrict__ w0, const float* __restrict__ w1,
                            const float* __restrict__ w2, const float* __restrict__ w3) {
    int i = blockIdx.x * blockDim.x + threadIdx.x;
    if (i < 4) g_loss[i] = 0.0;
    if (i < 4 * KCODES) {
        int g = i >> 9;
        int k = i & (KCODES - 1);
        const float* w = (g == 0) ? w0 : (g == 1) ? w1 : (g == 2) ? w2 : w3;
        const float* row = w + (size_t)k * KD;
        float s = 0.f;
        #pragma unroll 8
        for (int d = 0; d < KD; d++) {
            float v = row[d];
            s = __fadd_rn(s, __fmul_rn(v, v));   // mul-then-add like jnp.sum(W*W)
        }
        g_wsq[i] = s;
    }
}

// round-to-nearest-even of (rc0 + t) where rc0 is an integer (as float),
// t in [-0.5-eps, 0.5+eps] carries the exact fractional part.
__device__ __forceinline__ float rne_adjust(float rc0, float t) {
    float inc = 0.f;
    if (t > 0.5f) inc = 1.f;
    else if (t < -0.5f) inc = -1.f;
    else if (t == 0.5f) {               // tie: pick even neighbor
        float h = __fmul_rn(__fadd_rn(rc0, 1.f), 0.5f);
        inc = (h == rintf(h)) ? 1.f : 0.f;
    } else if (t == -0.5f) {
        float h = __fmul_rn(__fsub_rn(rc0, 1.f), 0.5f);
        inc = (h == rintf(h)) ? -1.f : 0.f;
    }
    return rc0 + inc;
}

__global__ __launch_bounds__(NTHREADS, 2)
void vq_kernel(const float* __restrict__ lat,
               const float* __restrict__ w0, const float* __restrict__ w1,
               const float* __restrict__ w2, const float* __restrict__ w3,
               float* __restrict__ out) {
    extern __shared__ char smraw[];
    SMem& sm = *reinterpret_cast<SMem*>(smraw);

    const int g  = blockIdx.y;
    const int t0blk = blockIdx.x * TM;
    const float* __restrict__ wg = (g == 0) ? w0 : (g == 1) ? w1 : (g == 2) ? w2 : w3;
    const int tid = threadIdx.x;
    const int tc = tid & 15;
    const int tr = tid >> 4;

    // ---- load X tile [128 tok x 128 d] -> transposed smem ----
    for (int i = tid; i < TM * 32; i += NTHREADS) {
        int tok = i >> 5;
        int d4  = i & 31;
        float4 v = *reinterpret_cast<const float4*>(
            lat + (size_t)(t0blk + tok) * 512 + (size_t)g * KD + d4 * 4);
        sm.X[d4 * 4 + 0][tok] = v.x;
        sm.X[d4 * 4 + 1][tok] = v.y;
        sm.X[d4 * 4 + 2][tok] = v.z;
        sm.X[d4 * 4 + 3][tok] = v.w;
    }
    __syncthreads();

    // ---- per-token: x_sq binade -> invU, 2*invU, boundary t0 ----
    if (tid < TM) {
        float s = 0.f;
        #pragma unroll 8
        for (int d = 0; d < KD; d++) {
            float v = sm.X[d][tid];
            s = fmaf(v, v, s);               // only the exponent matters
        }
        uint32_t b = __float_as_uint(s);
        uint32_t e = (b >> 23) & 0xFF;       // biased exponent of x_sq
        float iU  = __uint_as_float((277u - e) << 23);   // 2^(23-E)
        float pw  = __uint_as_float(e << 23);            // 2^E
        sm.invU[tid] = iU;
        sm.sc2[tid]  = __uint_as_float((278u - e) << 23);
        sm.t0[tid]   = __fmul_rn(__fsub_rn(pw, s), iU);  // exact (Sterbenz)
    }

    // per-thread token-row constants (loop-invariant across chunks)
    float iUr[8], sc2r[8], tt0r[8];
    int tokr[8];
    #pragma unroll
    for (int r = 0; r < 8; r++)
        tokr[r] = (r < 4) ? (tr * 4 + r) : (64 + tr * 4 + (r - 4));

    float best[8];
    int   bidx[8];
    #pragma unroll
    for (int r = 0; r < 8; r++) { best[r] = 3.4e38f; bidx[r] = 0; }

    bool got_const = false;

    for (int c = 0; c < KCODES / NC; c++) {
        __syncthreads();
        if (!got_const) {       // after first sync, sm.invU etc are visible
            #pragma unroll
            for (int r = 0; r < 8; r++) {
                iUr[r]  = sm.invU[tokr[r]];
                sc2r[r] = sm.sc2[tokr[r]];
                tt0r[r] = sm.t0[tokr[r]];
            }
            got_const = true;
        }
        // ---- load W chunk [64 codes x 128 d] -> transposed smem ----
        for (int i = tid; i < NC * 32; i += NTHREADS) {
            int n  = i >> 5;
            int d4 = i & 31;
            float4 v = *reinterpret_cast<const float4*>(
                wg + (size_t)(c * NC + n) * KD + d4 * 4);
            sm.W[d4 * 4 + 0][n] = v.x;
            sm.W[d4 * 4 + 1][n] = v.y;
            sm.W[d4 * 4 + 2][n] = v.z;
            sm.W[d4 * 4 + 3][n] = v.w;
        }
        if (tid < NC) sm.wsq[tid] = g_wsq[g * KCODES + c * NC + tid];
        __syncthreads();

        // ---- 8x4 register-tile: sequential fused-FMA over d=0..127 in order
        //      (matches the reference einsum's fp32 FMA accumulation) ----
        float acc[8][4];
        #pragma unroll
        for (int r = 0; r < 8; r++)
            #pragma unroll
            for (int j = 0; j < 4; j++) acc[r][j] = 0.f;

        #pragma unroll 4
        for (int k = 0; k < KD; k++) {
            float4 a0 = *reinterpret_cast<const float4*>(&sm.X[k][tr * 4]);
            float4 a1 = *reinterpret_cast<const float4*>(&sm.X[k][64 + tr * 4]);
            float4 bb = *reinterpret_cast<const float4*>(&sm.W[k][tc * 4]);
            float ai[8] = {a0.x, a0.y, a0.z, a0.w, a1.x, a1.y, a1.z, a1.w};
            float bj[4] = {bb.x, bb.y, bb.z, bb.w};
            #pragma unroll
            for (int r = 0; r < 8; r++)
                #pragma unroll
                for (int j = 0; j < 4; j++)
                    acc[r][j] = fmaf(ai[r], bj[j], acc[r][j]);
        }

        // ---- integer-grid scoring with exact half-even rounding ----
        float wq4[4];
        #pragma unroll
        for (int j = 0; j < 4; j++) wq4[j] = sm.wsq[tc * 4 + j];

        #pragma unroll
        for (int r = 0; r < 8; r++) {
            float iU = iUr[r], sc2v = sc2r[r], tt0 = tt0r[r];
            #pragma unroll
            for (int j = 0; j < 4; j++) {
                int kg = c * NC + tc * 4 + j;
                float m = rintf(__fmul_rn(wq4[j], iU));      // exact product (pow2)
                float z = __fmul_rn(acc[r][j], sc2v);        // 2*cross/u, exact
                // TwoSum(m, -z): s + err == m - z exactly
                float bn = -z;
                float s  = __fadd_rn(m, bn);
                float ap = __fsub_rn(s, bn);
                float bp = __fsub_rn(s, ap);
                float err = __fadd_rn(__fsub_rn(m, ap), __fsub_rn(bn, bp));
                float rc0 = rintf(s);
                float d   = __fsub_rn(s, rc0);               // exact
                float t   = __fadd_rn(d, err);
                float rc  = rne_adjust(rc0, t);
                float score = rc;
                if (rc <= tt0) {                 // rare: dist below 2^E -> half grid
                    float s2 = s + s, e2 = err + err;
                    float rf0 = rintf(s2);
                    float d2  = __fsub_rn(s2, rf0);
                    float t2  = __fadd_rn(d2, e2);
                    float rf  = rne_adjust(rf0, t2);
                    rf *= 0.5f;
                    score = (rf < tt0) ? rf : rc;
                }
                if (score < best[r]) { best[r] = score; bidx[r] = kg; }
            }
        }
    }

    // ---- argmin reduce across 16 tc-lanes (lowest index on ties) ----
    #pragma unroll
    for (int r = 0; r < 8; r++) {
        float s  = best[r];
        int   id = bidx[r];
        #pragma unroll
        for (int mk = 8; mk >= 1; mk >>= 1) {
            float so = __shfl_xor_sync(0xffffffffu, s,  mk);
            int   io = __shfl_xor_sync(0xffffffffu, id, mk);
            if (so < s || (so == s && io < id)) { s = so; id = io; }
        }
        if (tc == 0) sm.idx[tokr[r]] = id;
    }
    __syncthreads();

    // ---- gather codeword, out = fl(x + fl(q - x)), accumulate loss ----
    double lsum = 0.0;
    for (int i = tid; i < TM * 32; i += NTHREADS) {
        int tok = i >> 5;
        int d4  = i & 31;
        int id  = sm.idx[tok];
        float4 q = *reinterpret_cast<const float4*>(wg + (size_t)id * KD + d4 * 4);
        float x0 = sm.X[d4 * 4 + 0][tok];
        float x1 = sm.X[d4 * 4 + 1][tok];
        float x2 = sm.X[d4 * 4 + 2][tok];
        float x3 = sm.X[d4 * 4 + 3][tok];
        float e0 = __fsub_rn(q.x, x0), e1 = __fsub_rn(q.y, x1);
        float e2 = __fsub_rn(q.z, x2), e3 = __fsub_rn(q.w, x3);
        lsum += (double)e0 * e0 + (double)e1 * e1 + (double)e2 * e2 + (double)e3 * e3;
        float4 o;
        o.x = __fadd_rn(x0, e0); o.y = __fadd_rn(x1, e1);
        o.z = __fadd_rn(x2, e2); o.w = __fadd_rn(x3, e3);
        *reinterpret_cast<float4*>(
            out + (size_t)(t0blk + tok) * 512 + (size_t)g * KD + d4 * 4) = o;
    }

    #pragma unroll
    for (int mk = 16; mk >= 1; mk >>= 1)
        lsum += __shfl_down_sync(0xffffffffu, lsum, mk);
    if ((tid & 31) == 0) sm.lred[tid >> 5] = lsum;
    __syncthreads();
    if (tid == 0) {
        double t = 0.0;
        #pragma unroll
        for (int w = 0; w < NTHREADS / 32; w++) t += sm.lred[w];
        atomicAdd(&g_loss[g], t);
    }
}

__global__ void fin_kernel(float* __restrict__ out, int out_size, int T) {
    if (threadIdx.x == 0 && blockIdx.x == 0) {
        double s = 0.0;
        for (int g = 0; g < 4; g++) s += g_loss[g];
        double denom = (double)T * (double)KD;
        out[out_size - 1] = (float)(1.25 * s / denom);
    }
}

extern "C" void kernel_launch(void* const* d_in, const int* in_sizes, int n_in,
                              void* d_out, int out_size) {
    const float* lat = (const float*)d_in[0];
    const float* w1  = (const float*)d_in[1];
    const float* w2  = (const float*)d_in[2];
    const float* w3  = (const float*)d_in[3];
    const float* w4  = (const float*)d_in[4];
    float* out = (float*)d_out;
    const int T = in_sizes[0] / 512;

    size_t smem = sizeof(SMem);
    cudaFuncSetAttribute(vq_kernel, cudaFuncAttributeMaxDynamicSharedMemorySize, (int)smem);

    prep_kernel<<<8, 256>>>(w1, w2, w3, w4);

    dim3 grid(T / TM, 4);
    vq_kernel<<<grid, NTHREADS, smem>>>(lat, w1, w2, w3, w4, out);

    fin_kernel<<<1, 32>>>(out, out_size, T);
}